// round 6
// baseline (speedup 1.0000x reference)
#include <cuda_runtime.h>
#include <cstdint>
#include <cstddef>

#define TOKENS   131072
#define CDIM     96
#define NWIN     512
#define NTOK     256
#define HD       24
#define NHEADS   4
#define HIDDEN_DIM 384

typedef unsigned long long ull;

// Scratch (device globals)
__device__ float g_xw  [(size_t)TOKENS * CDIM];
__device__ float g_qkv [(size_t)3 * TOKENS * CDIM];
__device__ float g_attn[(size_t)TOKENS * CDIM];
__device__ float g_x2  [(size_t)TOKENS * CDIM];
__device__ float g_xn2 [(size_t)TOKENS * CDIM];
__device__ float g_h   [(size_t)TOKENS * HIDDEN_DIM];

__device__ __forceinline__ int nat_index(int t) {
    int r = t & 255, w = t >> 8;
    int b = w >> 8, wi = w & 255;
    int d  = ((((wi >> 6) & 3) << 2) | ((r >> 6) & 3));
    int hh = ((((wi >> 4) & 3) << 2) | ((r >> 4) & 3));
    int ww = ((((wi >> 2) & 3) << 2) | ((r >> 2) & 3));
    int tt = (((wi & 3) << 2) | (r & 3));
    d = (d + 2) & 15; hh = (hh + 2) & 15; ww = (ww + 2) & 15; tt = (tt + 2) & 15;
    return (((b * 16 + d) * 16 + hh) * 16 + ww) * 16 + tt;
}

__device__ __forceinline__ int group_of(int wi, int r) {
    int g = 0;
#pragma unroll
    for (int a = 3; a >= 0; --a) {
        int c = ((((wi >> (2 * a)) & 3) << 2) | ((r >> (2 * a)) & 3));
        int s = (c < 12) ? 0 : ((c < 14) ? 1 : 2);
        g = g * 3 + s;
    }
    return g;
}

// packed fp32x2 helpers (sm_103a)
__device__ __forceinline__ ull pk2(float a, float b) {
    ull r; asm("mov.b64 %0,{%1,%2};" : "=l"(r) : "f"(a), "f"(b)); return r;
}
__device__ __forceinline__ void fma2(ull& d, ull a, ull b) {
    asm("fma.rn.f32x2 %0,%1,%2,%0;" : "+l"(d) : "l"(a), "l"(b));
}
__device__ __forceinline__ void unpk2(float& a, float& b, ull v) {
    asm("mov.b64 {%0,%1},%2;" : "=f"(a), "=f"(b) : "l"(v));
}

__device__ __forceinline__ void mma_tf32(float4& d, const uint32_t a[4], const uint32_t b[2]) {
    asm("mma.sync.aligned.m16n8k8.row.col.f32.tf32.tf32.f32 "
        "{%0,%1,%2,%3},{%4,%5,%6,%7},{%8,%9},{%0,%1,%2,%3};"
        : "+f"(d.x), "+f"(d.y), "+f"(d.z), "+f"(d.w)
        : "r"(a[0]), "r"(a[1]), "r"(a[2]), "r"(a[3]), "r"(b[0]), "r"(b[1]));
}

// cp.async helpers
__device__ __forceinline__ void cp16(uint32_t dst, const void* src) {
    asm volatile("cp.async.cg.shared.global [%0],[%1],16;" :: "r"(dst), "l"(src));
}
__device__ __forceinline__ void cp_commit() { asm volatile("cp.async.commit_group;"); }
template <int N>
__device__ __forceinline__ void cp_wait() { asm volatile("cp.async.wait_group %0;" :: "n"(N)); }

// ---------------------------------------------------------------------------
// LayerNorm (warp per token); gather=1 fuses shift+window partition.
// ---------------------------------------------------------------------------
__global__ void ln_kernel(const float* __restrict__ x,
                          const float* __restrict__ gamma,
                          const float* __restrict__ beta,
                          float* __restrict__ out, int gather) {
    int t = blockIdx.x * 8 + (threadIdx.x >> 5);
    int lane = threadIdx.x & 31;
    int src = gather ? nat_index(t) : t;
    const float* row = x + (size_t)src * CDIM;
    float v0 = row[lane], v1 = row[lane + 32], v2 = row[lane + 64];
    float s = v0 + v1 + v2;
    float sq = v0 * v0 + v1 * v1 + v2 * v2;
#pragma unroll
    for (int o = 16; o; o >>= 1) {
        s  += __shfl_xor_sync(0xffffffffu, s, o);
        sq += __shfl_xor_sync(0xffffffffu, sq, o);
    }
    float mean = s * (1.f / 96.f);
    float var = sq * (1.f / 96.f) - mean * mean;
    float rstd = rsqrtf(var + 1e-5f);
    float* op = out + (size_t)t * CDIM;
    op[lane]      = (v0 - mean) * rstd * gamma[lane]      + beta[lane];
    op[lane + 32] = (v1 - mean) * rstd * gamma[lane + 32] + beta[lane + 32];
    op[lane + 64] = (v2 - mean) * rstd * gamma[lane + 64] + beta[lane + 64];
}

// ---------------------------------------------------------------------------
// tf32 GEMM with FRAGMENT-ORDERED W in smem (zero-bank-conflict b loads).
//   Bf[plane][ks][wnblk][ni][lane] = W[n0+wnblk*48+ni*8+(lane>>2)][ks*8+(lane&3)+plane*4]
//   WRES=1 (K=96): full Bf resident (9216 floats); A streams in 3-stage ring.
//   WRES=0 (fc2, K=384): Bf chunk streamed with A in the ring.
// BM=128, BN=96, 256 threads, warp tile 32x48, A stride 36 (conflict-free).
// fp32 bits fed to HMMA.TF32 (hw truncates mantissa).
// ---------------------------------------------------------------------------
#define ASTR 36

enum { EPI_QKV = 0, EPI_PROJ = 1, EPI_FC1 = 2, EPI_FC2 = 3 };

template <int E, bool WRES, int KD>
__global__ void __launch_bounds__(256, 2) gemm_bf(const float* __restrict__ A,
                                                  const float* __restrict__ W,
                                                  const float* __restrict__ bias,
                                                  const float* __restrict__ res,
                                                  float* __restrict__ out) {
    extern __shared__ float smem[];
    constexpr int ACH   = 128 * ASTR;          // 4608 floats / A chunk
    constexpr int WCH   = 2 * 4 * 2 * 6 * 32;  // 3072 floats / streamed W chunk
    constexpr int WRSZ  = 2 * 12 * 2 * 6 * 32; // 9216 floats resident Bf
    constexpr int NSTG  = 3, PF = 2;
    constexpr int STGSZ = WRES ? ACH : (ACH + WCH);
    constexpr int NC    = KD / 32;

    float* Bf   = smem;                        // resident table (WRES only)
    float* ring = WRES ? smem + WRSZ : smem;

    const int tid  = threadIdx.x;
    const int warp = tid >> 5, lane = tid & 31;
    const int gid  = lane >> 2, tig = lane & 3;
    const int wm   = (warp >> 1) * 32;
    const int wb   = warp & 1;                 // n-half of warp (0: n<48, 1: n>=48)
    const int m0   = blockIdx.x * 128;
    const int n0   = blockIdx.y * 96;

    uint32_t ring_u = (uint32_t)__cvta_generic_to_shared(ring);
    uint32_t bf_u   = (uint32_t)__cvta_generic_to_shared(Bf);

    // ---- stage resident Bf (2304 cp16, 9/thread) ----
    if (WRES) {
#pragma unroll
        for (int it = 0; it < 9; ++it) {
            int q = tid + it * 256;
            int g = q & 7; int q1 = q >> 3;
            int ni = q1 % 6; q1 /= 6;
            int blk = q1 & 1; q1 >>= 1;
            int ks = q1 % 12, pl = q1 / 12;
            const float* src = W + (size_t)(n0 + blk * 48 + ni * 8 + g) * KD + ks * 8 + pl * 4;
            uint32_t dst = bf_u + (((pl * 12 + ks) * 384) + blk * 192 + ni * 32 + g * 4) * 4;
            cp16(dst, src);
        }
    }

    auto issue = [&](int c) {
        int s = c % NSTG, kc = c * 32;
        uint32_t abuf = ring_u + (s * STGSZ) * 4;
        const int crow = tid >> 3, cc4 = (tid & 7) << 2;
#pragma unroll
        for (int it = 0; it < 4; ++it) {
            int row = crow + it * 32;
            cp16(abuf + (row * ASTR + cc4) * 4, A + (size_t)(m0 + row) * KD + kc + cc4);
        }
        if (!WRES) {
            uint32_t wbuf = abuf + ACH * 4;
#pragma unroll
            for (int it = 0; it < 3; ++it) {
                int q = tid + it * 256;
                int g = q & 7; int q1 = q >> 3;
                int ni = q1 % 6; q1 /= 6;
                int blk = q1 & 1; q1 >>= 1;
                int ks = q1 & 3, pl = q1 >> 2;
                const float* src = W + (size_t)(n0 + blk * 48 + ni * 8 + g) * KD + kc + ks * 8 + pl * 4;
                cp16(wbuf + (((pl * 4 + ks) * 384) + blk * 192 + ni * 32 + g * 4) * 4, src);
            }
        }
    };

    issue(0); cp_commit();     // G0 = Bf (if WRES) + chunk0
    issue(1); cp_commit();     // G1 = chunk1

    float4 acc[2][6];
#pragma unroll
    for (int i = 0; i < 2; ++i)
#pragma unroll
        for (int j = 0; j < 6; ++j) acc[i][j] = make_float4(0.f, 0.f, 0.f, 0.f);

    for (int c = 0; c < NC; ++c) {
        if (c + PF < NC) issue(c + PF);
        cp_commit();
        cp_wait<PF>();
        __syncthreads();

        const uint32_t* As = (const uint32_t*)(ring + (c % NSTG) * STGSZ);
        const uint32_t* Wf = WRES ? (const uint32_t*)Bf
                                  : (const uint32_t*)(ring + (c % NSTG) * STGSZ + ACH);
        const int plo = WRES ? (12 * 384) : (4 * 384);

#pragma unroll
        for (int ks4 = 0; ks4 < 4; ++ks4) {
            const int k = ks4 * 8;
            const int ksg = WRES ? (c * 4 + ks4) : ks4;
            const int bbase = ksg * 384 + wb * 192 + lane;

            uint32_t a[2][4];
#pragma unroll
            for (int mi = 0; mi < 2; ++mi) {
                int r = wm + mi * 16 + gid;
                a[mi][0] = As[r * ASTR + k + tig];
                a[mi][1] = As[(r + 8) * ASTR + k + tig];
                a[mi][2] = As[r * ASTR + k + tig + 4];
                a[mi][3] = As[(r + 8) * ASTR + k + tig + 4];
            }
            uint32_t b[6][2];
#pragma unroll
            for (int ni = 0; ni < 6; ++ni) {
                b[ni][0] = Wf[bbase + ni * 32];
                b[ni][1] = Wf[plo + bbase + ni * 32];
            }
#pragma unroll
            for (int mi = 0; mi < 2; ++mi)
#pragma unroll
                for (int ni = 0; ni < 6; ++ni) mma_tf32(acc[mi][ni], a[mi], b[ni]);
        }
        __syncthreads();
    }

    // ---- fused epilogues ---- (warp n-offset = wb*48; cols = wb*48 + ni*8 + tig*2 + e)
    const int wn = wb * 48;
#pragma unroll
    for (int mi = 0; mi < 2; ++mi) {
        int r0 = m0 + wm + mi * 16 + gid;
#pragma unroll
        for (int half = 0; half < 2; ++half) {
            int m = r0 + half * 8;
            size_t proj_dst = 0;
            if (E == EPI_PROJ) proj_dst = (size_t)nat_index(m) * CDIM;
            int w = m >> 8, rr = m & 255;
#pragma unroll
            for (int ni = 0; ni < 6; ++ni) {
                float v0 = half ? acc[mi][ni].z : acc[mi][ni].x;
                float v1 = half ? acc[mi][ni].w : acc[mi][ni].y;
#pragma unroll
                for (int e = 0; e < 2; ++e) {
                    int nl = wn + ni * 8 + tig * 2 + e;
                    float v = (e ? v1 : v0) + bias[n0 + nl];
                    if (E == EPI_QKV) {
                        const float scale = (blockIdx.y == 0) ? 0.20412414523193154f : 1.0f;
                        int h = nl / 24, dd = nl % 24;
                        out[(((size_t)blockIdx.y * NWIN + w) * NHEADS + h) * (NTOK * HD) + rr * HD + dd] = v * scale;
                    } else if (E == EPI_PROJ) {
                        out[proj_dst + nl] = res[proj_dst + nl] + v;
                    } else if (E == EPI_FC1) {
                        float gel = 0.5f * v * (1.f + erff(v * 0.70710678118654752f));
                        out[(size_t)m * HIDDEN_DIM + n0 + nl] = gel;
                    } else {
                        out[(size_t)m * CDIM + nl] = res[(size_t)m * CDIM + nl] + v;
                    }
                }
            }
        }
    }
}

// ---------------------------------------------------------------------------
// Attention: block per (window, head); thread = query row; packed fp32x2.
// ---------------------------------------------------------------------------
__global__ void __launch_bounds__(256) attn_kernel(const float* __restrict__ qkv,
                                                   float* __restrict__ attnout) {
    extern __shared__ float sm[];
    float* ks = sm;
    float* vs = sm + NTOK * HD;
    unsigned char* grp = (unsigned char*)(sm + 2 * NTOK * HD);

    const int w = blockIdx.x, h = blockIdx.y;
    const int tid = threadIdx.x;
    const size_t head_stride = (size_t)NTOK * HD;
    const float* kbase = qkv + (((size_t)1 * NWIN + w) * NHEADS + h) * head_stride;
    const float* vbase = qkv + (((size_t)2 * NWIN + w) * NHEADS + h) * head_stride;

#pragma unroll
    for (int it = 0; it < 6; ++it) {
        int idx = (tid + it * 256) * 4;
        *(float4*)(ks + idx) = *(const float4*)(kbase + idx);
        *(float4*)(vs + idx) = *(const float4*)(vbase + idx);
    }
    grp[tid] = (unsigned char)group_of(w & 255, tid);
    __syncthreads();

    const float* qrow = qkv + (((size_t)0 * NWIN + w) * NHEADS + h) * head_stride + tid * HD;
    ull q2[12];
#pragma unroll
    for (int i = 0; i < 12; ++i) {
        float2 v = *(const float2*)(qrow + 2 * i);
        q2[i] = pk2(v.x, v.y);
    }
    const int gi = grp[tid];

    ull o2[12];
#pragma unroll
    for (int i = 0; i < 12; ++i) o2[i] = 0ULL;
    float l = 0.f;

    const ull* ksm = (const ull*)ks;
    const ull* vsm = (const ull*)vs;

    for (int j = 0; j < NTOK; ++j) {
        const ull* k2 = ksm + j * 12;
        ull dp = 0ULL;
#pragma unroll
        for (int i = 0; i < 12; ++i) fma2(dp, q2[i], k2[i]);
        float slo, shi; unpk2(slo, shi, dp);
        float s = slo + shi;
        s = (grp[j] == gi) ? s : s - 100.f;
        float p = __expf(s);
        l += p;
        ull pp = pk2(p, p);
        const ull* v2 = vsm + j * 12;
#pragma unroll
        for (int i = 0; i < 12; ++i) fma2(o2[i], pp, v2[i]);
    }
    float inv = 1.f / l;
    float* op = attnout + ((size_t)w * NTOK + tid) * CDIM + h * HD;
#pragma unroll
    for (int i = 0; i < 12; ++i) {
        float a, b; unpk2(a, b, o2[i]);
        op[2 * i] = a * inv; op[2 * i + 1] = b * inv;
    }
}

// ---------------------------------------------------------------------------
extern "C" void kernel_launch(void* const* d_in, const int* in_sizes, int n_in,
                              void* d_out, int out_size) {
    (void)in_sizes; (void)n_in; (void)out_size;
    const float* x       = (const float*)d_in[0];
    const float* norm1_g = (const float*)d_in[2];
    const float* norm1_b = (const float*)d_in[3];
    const float* qkv_w   = (const float*)d_in[4];
    const float* qkv_b   = (const float*)d_in[5];
    const float* proj_w  = (const float*)d_in[6];
    const float* proj_b  = (const float*)d_in[7];
    const float* norm2_g = (const float*)d_in[8];
    const float* norm2_b = (const float*)d_in[9];
    const float* fc1_w   = (const float*)d_in[10];
    const float* fc1_b   = (const float*)d_in[11];
    const float* fc2_w   = (const float*)d_in[12];
    const float* fc2_b   = (const float*)d_in[13];
    float* out = (float*)d_out;

    float *xw, *qkv, *attn, *x2, *xn2, *hbuf;
    cudaGetSymbolAddress((void**)&xw,   g_xw);
    cudaGetSymbolAddress((void**)&qkv,  g_qkv);
    cudaGetSymbolAddress((void**)&attn, g_attn);
    cudaGetSymbolAddress((void**)&x2,   g_x2);
    cudaGetSymbolAddress((void**)&xn2,  g_xn2);
    cudaGetSymbolAddress((void**)&hbuf, g_h);

    // smem: WRES: 9216 + 3*4608 = 23040 floats; fc2: 3*(4608+3072) = 23040 floats
    const int gsmem = 23040 * 4;  // 92160 B
    cudaFuncSetAttribute(gemm_bf<EPI_QKV,  true,  96 >, cudaFuncAttributeMaxDynamicSharedMemorySize, gsmem);
    cudaFuncSetAttribute(gemm_bf<EPI_PROJ, true,  96 >, cudaFuncAttributeMaxDynamicSharedMemorySize, gsmem);
    cudaFuncSetAttribute(gemm_bf<EPI_FC1,  true,  96 >, cudaFuncAttributeMaxDynamicSharedMemorySize, gsmem);
    cudaFuncSetAttribute(gemm_bf<EPI_FC2,  false, 384>, cudaFuncAttributeMaxDynamicSharedMemorySize, gsmem);

    const int attn_smem = (2 * NTOK * HD) * 4 + 256;
    cudaFuncSetAttribute(attn_kernel, cudaFuncAttributeMaxDynamicSharedMemorySize, attn_smem);

    ln_kernel<<<TOKENS / 8, 256>>>(x, norm1_g, norm1_b, xw, 1);
    gemm_bf<EPI_QKV, true, 96><<<dim3(1024, 3), 256, gsmem>>>(xw, qkv_w, qkv_b, nullptr, qkv);
    attn_kernel<<<dim3(NWIN, NHEADS), 256, attn_smem>>>(qkv, attn);
    gemm_bf<EPI_PROJ, true, 96><<<dim3(1024, 1), 256, gsmem>>>(attn, proj_w, proj_b, x, x2);
    ln_kernel<<<TOKENS / 8, 256>>>(x2, norm2_g, norm2_b, xn2, 0);
    gemm_bf<EPI_FC1, true, 96><<<dim3(1024, 4), 256, gsmem>>>(xn2, fc1_w, fc1_b, nullptr, hbuf);
    gemm_bf<EPI_FC2, false, 384><<<dim3(1024, 1), 256, gsmem>>>(hbuf, fc2_w, fc2_b, x2, out);
}

// round 8
// speedup vs baseline: 1.1255x; 1.1255x over previous
#include <cuda_runtime.h>
#include <cstdint>
#include <cstddef>

#define TOKENS   131072
#define CDIM     96
#define NWIN     512
#define NTOK     256
#define HD       24
#define NHEADS   4
#define HIDDEN_DIM 384

typedef unsigned long long ull;

// Scratch (device globals)
__device__ float g_qkv [(size_t)3 * TOKENS * CDIM];
__device__ float g_attn[(size_t)TOKENS * CDIM];
__device__ float g_x2  [(size_t)TOKENS * CDIM];
__device__ float g_h   [(size_t)TOKENS * HIDDEN_DIM];

__device__ __forceinline__ int nat_index(int t) {
    int r = t & 255, w = t >> 8;
    int b = w >> 8, wi = w & 255;
    int d  = ((((wi >> 6) & 3) << 2) | ((r >> 6) & 3));
    int hh = ((((wi >> 4) & 3) << 2) | ((r >> 4) & 3));
    int ww = ((((wi >> 2) & 3) << 2) | ((r >> 2) & 3));
    int tt = (((wi & 3) << 2) | (r & 3));
    d = (d + 2) & 15; hh = (hh + 2) & 15; ww = (ww + 2) & 15; tt = (tt + 2) & 15;
    return (((b * 16 + d) * 16 + hh) * 16 + ww) * 16 + tt;
}

__device__ __forceinline__ int group_of(int wi, int r) {
    int g = 0;
#pragma unroll
    for (int a = 3; a >= 0; --a) {
        int c = ((((wi >> (2 * a)) & 3) << 2) | ((r >> (2 * a)) & 3));
        int s = (c < 12) ? 0 : ((c < 14) ? 1 : 2);
        g = g * 3 + s;
    }
    return g;
}

// packed fp32x2 helpers (sm_103a)
__device__ __forceinline__ ull pk2(float a, float b) {
    ull r; asm("mov.b64 %0,{%1,%2};" : "=l"(r) : "f"(a), "f"(b)); return r;
}
__device__ __forceinline__ void fma2(ull& d, ull a, ull b) {
    asm("fma.rn.f32x2 %0,%1,%2,%0;" : "+l"(d) : "l"(a), "l"(b));
}
__device__ __forceinline__ void unpk2(float& a, float& b, ull v) {
    asm("mov.b64 {%0,%1},%2;" : "=f"(a), "=f"(b) : "l"(v));
}

__device__ __forceinline__ void mma_tf32(float4& d, const uint32_t a[4], const uint32_t b[2]) {
    asm("mma.sync.aligned.m16n8k8.row.col.f32.tf32.tf32.f32 "
        "{%0,%1,%2,%3},{%4,%5,%6,%7},{%8,%9},{%0,%1,%2,%3};"
        : "+f"(d.x), "+f"(d.y), "+f"(d.z), "+f"(d.w)
        : "r"(a[0]), "r"(a[1]), "r"(a[2]), "r"(a[3]), "r"(b[0]), "r"(b[1]));
}

// cp.async helpers
__device__ __forceinline__ void cp16(uint32_t dst, const void* src) {
    asm volatile("cp.async.cg.shared.global [%0],[%1],16;" :: "r"(dst), "l"(src));
}
__device__ __forceinline__ void cp_commit() { asm volatile("cp.async.commit_group;"); }
template <int N>
__device__ __forceinline__ void cp_wait() { asm volatile("cp.async.wait_group %0;" :: "n"(N)); }

enum { EPI_QKV = 0, EPI_PROJ = 1, EPI_FC1 = 2, EPI_FC2 = 3 };

// W tile layout: [96 rows][32 floats], 16B-chunk swizzled: chunk j of row n is
// stored at chunk position (j + n) & 7.  B-frag loads are conflict-free:
// bank = 4*((2ks+p+gid)&7) + tig, distinct for all 32 lanes.

// ---------------------------------------------------------------------------
// A-resident tf32 GEMM.  A (128 x 96 fp32) staged once per CTA (optionally
// LayerNorm'ed in smem, optionally gathered via nat_index).  W streamed in
// swizzled 96x32 chunks, 2-stage cp.async ring (1-deep prefetch = safe),
// NB n-blocks per CTA.  fp32 bits fed to HMMA.TF32 (hw truncates mantissa).
// ---------------------------------------------------------------------------
#define ASTR2 100

template <int E, bool LNF, bool GATHER, int NB>
__global__ void __launch_bounds__(256, 2) gemm_fz(const float* __restrict__ A,
                                                  const float* __restrict__ W,
                                                  const float* __restrict__ bias,
                                                  const float* __restrict__ res,
                                                  const float* __restrict__ gamma,
                                                  const float* __restrict__ beta,
                                                  float* __restrict__ out) {
    extern __shared__ float smem[];
    float* As   = smem;                       // [128][100] fp32
    float* ring = smem + 128 * ASTR2;         // 2 x [96][32] swizzled W
    constexpr int WCH = 96 * 32;
    constexpr int NC  = NB * 3;

    const int tid  = threadIdx.x;
    const int warp = tid >> 5, lane = tid & 31;
    const int gid  = lane >> 2, tig = lane & 3;
    const int wm   = (warp >> 1) * 32;
    const int wb   = warp & 1;
    const int wn   = wb * 48;
    const int m0   = blockIdx.x * 128;

    uint32_t as_u   = (uint32_t)__cvta_generic_to_shared(As);
    uint32_t ring_u = (uint32_t)__cvta_generic_to_shared(ring);

    // ---- stage A (3072 cp16, 12/thread) ----
#pragma unroll
    for (int it = 0; it < 12; ++it) {
        int idx = tid + it * 256;
        int row = idx / 24, c4 = (idx % 24) << 2;
        int m = m0 + row;
        const float* src = A + (size_t)(GATHER ? nat_index(m) : m) * CDIM + c4;
        cp16(as_u + (row * ASTR2 + c4) * 4, src);
    }
    cp_commit();                              // group: A

    const int wrow = tid >> 3, wj = tid & 7;  // W copy slot: 16B chunk wj of row
    auto issueW = [&](int c) {
        uint32_t wbuf = ring_u + ((c & 1) * WCH) * 4;
        int n0 = (c / 3) * 96, kc = (c % 3) * 32;
#pragma unroll
        for (int it = 0; it < 3; ++it) {
            int r = wrow + it * 32;
            uint32_t dst = wbuf + (r * 32 + (((wj + r) & 7) << 2)) * 4;
            cp16(dst, W + (size_t)(n0 + r) * CDIM + kc + (wj << 2));
        }
    };
    issueW(0); cp_commit();                   // group: W0

    if (LNF) {
        cp_wait<1>();                         // A complete (W0 may be pending)
        __syncthreads();
        int row = tid >> 1, half = tid & 1;
        float s = 0.f, sq = 0.f;
#pragma unroll
        for (int i = 0; i < 48; ++i) {
            float v = As[row * ASTR2 + half * 48 + i];
            s += v; sq += v * v;
        }
        s  += __shfl_xor_sync(0xffffffffu, s, 1);
        sq += __shfl_xor_sync(0xffffffffu, sq, 1);
        float mean = s * (1.f / 96.f);
        float var  = sq * (1.f / 96.f) - mean * mean;
        float rstd = rsqrtf(var + 1e-5f);
#pragma unroll
        for (int i = 0; i < 48; ++i) {
            int col = half * 48 + i;
            As[row * ASTR2 + col] = (As[row * ASTR2 + col] - mean) * rstd * __ldg(gamma + col) + __ldg(beta + col);
        }
        __syncthreads();
    }

    const uint32_t* Asu = (const uint32_t*)As;

    float4 acc[2][6];
#pragma unroll
    for (int i = 0; i < 2; ++i)
#pragma unroll
        for (int j = 0; j < 6; ++j) acc[i][j] = make_float4(0.f, 0.f, 0.f, 0.f);

    for (int c = 0; c < NC; ++c) {
        if (c + 1 < NC) issueW(c + 1);
        cp_commit();
        cp_wait<1>();                         // chunk c (and A) complete
        __syncthreads();

        const uint32_t* Ws = (const uint32_t*)(ring + (c & 1) * WCH);

#pragma unroll
        for (int ks4 = 0; ks4 < 4; ++ks4) {
            const int kg = (c % 3) * 32 + ks4 * 8;
            uint32_t a[2][4];
#pragma unroll
            for (int mi = 0; mi < 2; ++mi) {
                int r = wm + mi * 16 + gid;
                a[mi][0] = Asu[r * ASTR2 + kg + tig];
                a[mi][1] = Asu[(r + 8) * ASTR2 + kg + tig];
                a[mi][2] = Asu[r * ASTR2 + kg + tig + 4];
                a[mi][3] = Asu[(r + 8) * ASTR2 + kg + tig + 4];
            }
            uint32_t b[6][2];
#pragma unroll
            for (int ni = 0; ni < 6; ++ni) {
                int n = wn + ni * 8 + gid;
                int ch0 = (2 * ks4 + gid) & 7;          // n&7 == gid
                int ch1 = (2 * ks4 + 1 + gid) & 7;
                b[ni][0] = Ws[n * 32 + (ch0 << 2) + tig];
                b[ni][1] = Ws[n * 32 + (ch1 << 2) + tig];
            }
#pragma unroll
            for (int mi = 0; mi < 2; ++mi)
#pragma unroll
                for (int ni = 0; ni < 6; ++ni) mma_tf32(acc[mi][ni], a[mi], b[ni]);
        }

        if ((c % 3) == 2) {
            // ---- epilogue for n-block nb = c/3 ----
            const int nb = c / 3, n0 = nb * 96;
#pragma unroll
            for (int mi = 0; mi < 2; ++mi) {
                int r0 = m0 + wm + mi * 16 + gid;
#pragma unroll
                for (int half = 0; half < 2; ++half) {
                    int m = r0 + half * 8;
                    size_t proj_dst = 0;
                    if (E == EPI_PROJ) proj_dst = (size_t)nat_index(m) * CDIM;
                    int w = m >> 8, rr = m & 255;
#pragma unroll
                    for (int ni = 0; ni < 6; ++ni) {
                        float v0 = half ? acc[mi][ni].z : acc[mi][ni].x;
                        float v1 = half ? acc[mi][ni].w : acc[mi][ni].y;
#pragma unroll
                        for (int e = 0; e < 2; ++e) {
                            int nl = wn + ni * 8 + tig * 2 + e;
                            float v = (e ? v1 : v0) + bias[n0 + nl];
                            if (E == EPI_QKV) {
                                const float scale = (nb == 0) ? 0.20412414523193154f : 1.0f;
                                int h = nl / 24, dd = nl % 24;
                                out[(((size_t)nb * NWIN + w) * NHEADS + h) * (NTOK * HD) + rr * HD + dd] = v * scale;
                            } else if (E == EPI_PROJ) {
                                out[proj_dst + nl] = res[proj_dst + nl] + v;
                            } else if (E == EPI_FC1) {
                                float gel = 0.5f * v * (1.f + erff(v * 0.70710678118654752f));
                                out[(size_t)m * HIDDEN_DIM + n0 + nl] = gel;
                            } else {
                                out[(size_t)m * CDIM + nl] = res[(size_t)m * CDIM + nl] + v;
                            }
                        }
                    }
                }
            }
            if (c + 1 < NC) {
#pragma unroll
                for (int i = 0; i < 2; ++i)
#pragma unroll
                    for (int j = 0; j < 6; ++j) acc[i][j] = make_float4(0.f, 0.f, 0.f, 0.f);
            }
        }
        __syncthreads();                      // stage reads done before reuse
    }
}

// ---------------------------------------------------------------------------
// Streaming tf32 GEMM for fc2 (K=384): A + swizzled-W chunks.
// 3-stage ring with 2-deep prefetch: write stage (c+2)%3 never aliases the
// read stage c%3 nor the previous iteration's stage (fixes R7 race).
// ---------------------------------------------------------------------------
#define ASTR 36

__global__ void __launch_bounds__(256, 2) gemm_fc2(const float* __restrict__ A,
                                                   const float* __restrict__ W,
                                                   const float* __restrict__ bias,
                                                   const float* __restrict__ res,
                                                   float* __restrict__ out) {
    extern __shared__ float smem[];
    constexpr int ACH = 128 * ASTR, WCH = 96 * 32, STG = ACH + WCH;
    constexpr int KD = HIDDEN_DIM, NC = KD / 32, NSTG = 3, PF = 2;

    const int tid  = threadIdx.x;
    const int warp = tid >> 5, lane = tid & 31;
    const int gid  = lane >> 2, tig = lane & 3;
    const int wm   = (warp >> 1) * 32;
    const int wb   = warp & 1;
    const int wn   = wb * 48;
    const int m0   = blockIdx.x * 128;

    uint32_t smem_u = (uint32_t)__cvta_generic_to_shared(smem);
    const int crow = tid >> 3, cj = tid & 7, cc4 = cj << 2;

    auto issue = [&](int c) {
        int s = c % NSTG, kc = c * 32;
        uint32_t abuf = smem_u + (s * STG) * 4;
#pragma unroll
        for (int it = 0; it < 4; ++it) {
            int row = crow + it * 32;
            cp16(abuf + (row * ASTR + cc4) * 4, A + (size_t)(m0 + row) * KD + kc + cc4);
        }
        uint32_t wbuf = abuf + ACH * 4;
#pragma unroll
        for (int it = 0; it < 3; ++it) {
            int r = crow + it * 32;
            cp16(wbuf + (r * 32 + (((cj + r) & 7) << 2)) * 4,
                 W + (size_t)r * KD + kc + cc4);
        }
    };

    issue(0); cp_commit();
    issue(1); cp_commit();

    float4 acc[2][6];
#pragma unroll
    for (int i = 0; i < 2; ++i)
#pragma unroll
        for (int j = 0; j < 6; ++j) acc[i][j] = make_float4(0.f, 0.f, 0.f, 0.f);

    for (int c = 0; c < NC; ++c) {
        if (c + PF < NC) issue(c + PF);
        cp_commit();
        cp_wait<PF>();
        __syncthreads();

        const uint32_t* As = (const uint32_t*)(smem + (c % NSTG) * STG);
        const uint32_t* Ws = (const uint32_t*)(smem + (c % NSTG) * STG + ACH);

#pragma unroll
        for (int ks4 = 0; ks4 < 4; ++ks4) {
            const int k = ks4 * 8;
            uint32_t a[2][4];
#pragma unroll
            for (int mi = 0; mi < 2; ++mi) {
                int r = wm + mi * 16 + gid;
                a[mi][0] = As[r * ASTR + k + tig];
                a[mi][1] = As[(r + 8) * ASTR + k + tig];
                a[mi][2] = As[r * ASTR + k + tig + 4];
                a[mi][3] = As[(r + 8) * ASTR + k + tig + 4];
            }
            uint32_t b[6][2];
#pragma unroll
            for (int ni = 0; ni < 6; ++ni) {
                int n = wn + ni * 8 + gid;
                int ch0 = (2 * ks4 + gid) & 7;
                int ch1 = (2 * ks4 + 1 + gid) & 7;
                b[ni][0] = Ws[n * 32 + (ch0 << 2) + tig];
                b[ni][1] = Ws[n * 32 + (ch1 << 2) + tig];
            }
#pragma unroll
            for (int mi = 0; mi < 2; ++mi)
#pragma unroll
                for (int ni = 0; ni < 6; ++ni) mma_tf32(acc[mi][ni], a[mi], b[ni]);
        }
        __syncthreads();
    }

#pragma unroll
    for (int mi = 0; mi < 2; ++mi) {
        int r0 = m0 + wm + mi * 16 + gid;
#pragma unroll
        for (int half = 0; half < 2; ++half) {
            int m = r0 + half * 8;
#pragma unroll
            for (int ni = 0; ni < 6; ++ni) {
                float v0 = half ? acc[mi][ni].z : acc[mi][ni].x;
                float v1 = half ? acc[mi][ni].w : acc[mi][ni].y;
#pragma unroll
                for (int e = 0; e < 2; ++e) {
                    int nl = wn + ni * 8 + tig * 2 + e;
                    float v = (e ? v1 : v0) + bias[nl];
                    out[(size_t)m * CDIM + nl] = res[(size_t)m * CDIM + nl] + v;
                }
            }
        }
    }
}

// ---------------------------------------------------------------------------
// Attention: block per (window, head); thread = query row; packed fp32x2.
// ---------------------------------------------------------------------------
__global__ void __launch_bounds__(256) attn_kernel(const float* __restrict__ qkv,
                                                   float* __restrict__ attnout) {
    extern __shared__ float sm[];
    float* ks = sm;
    float* vs = sm + NTOK * HD;
    unsigned char* grp = (unsigned char*)(sm + 2 * NTOK * HD);

    const int w = blockIdx.x, h = blockIdx.y;
    const int tid = threadIdx.x;
    const size_t head_stride = (size_t)NTOK * HD;
    const float* kbase = qkv + (((size_t)1 * NWIN + w) * NHEADS + h) * head_stride;
    const float* vbase = qkv + (((size_t)2 * NWIN + w) * NHEADS + h) * head_stride;

#pragma unroll
    for (int it = 0; it < 6; ++it) {
        int idx = (tid + it * 256) * 4;
        *(float4*)(ks + idx) = *(const float4*)(kbase + idx);
        *(float4*)(vs + idx) = *(const float4*)(vbase + idx);
    }
    grp[tid] = (unsigned char)group_of(w & 255, tid);
    __syncthreads();

    const float* qrow = qkv + (((size_t)0 * NWIN + w) * NHEADS + h) * head_stride + tid * HD;
    ull q2[12];
#pragma unroll
    for (int i = 0; i < 12; ++i) {
        float2 v = *(const float2*)(qrow + 2 * i);
        q2[i] = pk2(v.x, v.y);
    }
    const int gi = grp[tid];

    ull o2[12];
#pragma unroll
    for (int i = 0; i < 12; ++i) o2[i] = 0ULL;
    float l = 0.f;

    const ull* ksm = (const ull*)ks;
    const ull* vsm = (const ull*)vs;

    for (int j = 0; j < NTOK; ++j) {
        const ull* k2 = ksm + j * 12;
        ull dp = 0ULL;
#pragma unroll
        for (int i = 0; i < 12; ++i) fma2(dp, q2[i], k2[i]);
        float slo, shi; unpk2(slo, shi, dp);
        float s = slo + shi;
        s = (grp[j] == gi) ? s : s - 100.f;
        float p = __expf(s);
        l += p;
        ull pp = pk2(p, p);
        const ull* v2 = vsm + j * 12;
#pragma unroll
        for (int i = 0; i < 12; ++i) fma2(o2[i], pp, v2[i]);
    }
    float inv = 1.f / l;
    float* op = attnout + ((size_t)w * NTOK + tid) * CDIM + h * HD;
#pragma unroll
    for (int i = 0; i < 12; ++i) {
        float a, b; unpk2(a, b, o2[i]);
        op[2 * i] = a * inv; op[2 * i + 1] = b * inv;
    }
}

// ---------------------------------------------------------------------------
extern "C" void kernel_launch(void* const* d_in, const int* in_sizes, int n_in,
                              void* d_out, int out_size) {
    (void)in_sizes; (void)n_in; (void)out_size;
    const float* x       = (const float*)d_in[0];
    const float* norm1_g = (const float*)d_in[2];
    const float* norm1_b = (const float*)d_in[3];
    const float* qkv_w   = (const float*)d_in[4];
    const float* qkv_b   = (const float*)d_in[5];
    const float* proj_w  = (const float*)d_in[6];
    const float* proj_b  = (const float*)d_in[7];
    const float* norm2_g = (const float*)d_in[8];
    const float* norm2_b = (const float*)d_in[9];
    const float* fc1_w   = (const float*)d_in[10];
    const float* fc1_b   = (const float*)d_in[11];
    const float* fc2_w   = (const float*)d_in[12];
    const float* fc2_b   = (const float*)d_in[13];
    float* out = (float*)d_out;

    float *qkv, *attn, *x2, *hbuf;
    cudaGetSymbolAddress((void**)&qkv,  g_qkv);
    cudaGetSymbolAddress((void**)&attn, g_attn);
    cudaGetSymbolAddress((void**)&x2,   g_x2);
    cudaGetSymbolAddress((void**)&hbuf, g_h);

    const int fz_smem  = (128 * ASTR2 + 2 * 96 * 32) * 4;            // 75776 B
    const int fc2_smem = 3 * (128 * ASTR + 96 * 32) * 4;             // 92160 B
    cudaFuncSetAttribute(gemm_fz<EPI_QKV,  true,  true,  3>, cudaFuncAttributeMaxDynamicSharedMemorySize, fz_smem);
    cudaFuncSetAttribute(gemm_fz<EPI_PROJ, false, false, 1>, cudaFuncAttributeMaxDynamicSharedMemorySize, fz_smem);
    cudaFuncSetAttribute(gemm_fz<EPI_FC1,  true,  false, 4>, cudaFuncAttributeMaxDynamicSharedMemorySize, fz_smem);
    cudaFuncSetAttribute(gemm_fc2, cudaFuncAttributeMaxDynamicSharedMemorySize, fc2_smem);

    const int attn_smem = (2 * NTOK * HD) * 4 + 256;
    cudaFuncSetAttribute(attn_kernel, cudaFuncAttributeMaxDynamicSharedMemorySize, attn_smem);

    // 1) QKV: fused LN1 + shift + partition (gather), all 3 N-blocks per CTA
    gemm_fz<EPI_QKV, true, true, 3><<<1024, 256, fz_smem>>>(
        x, qkv_w, qkv_b, nullptr, norm1_g, norm1_b, qkv);
    // 2) windowed attention, analytic shift mask
    attn_kernel<<<dim3(NWIN, NHEADS), 256, attn_smem>>>(qkv, attn);
    // 3) proj + reverse partition/shift + residual
    gemm_fz<EPI_PROJ, false, false, 1><<<1024, 256, fz_smem>>>(
        attn, proj_w, proj_b, x, nullptr, nullptr, x2);
    // 4) fc1: fused LN2 + exact GELU, all 4 N-blocks per CTA
    gemm_fz<EPI_FC1, true, false, 4><<<1024, 256, fz_smem>>>(
        x2, fc1_w, fc1_b, nullptr, norm2_g, norm2_b, hbuf);
    // 5) fc2 + residual -> output
    gemm_fc2<<<1024, 256, fc2_smem>>>(hbuf, fc2_w, fc2_b, x2, out);
}

// round 9
// speedup vs baseline: 1.6684x; 1.4823x over previous
#include <cuda_runtime.h>
#include <cstdint>
#include <cstddef>

#define TOKENS   131072
#define CDIM     96
#define NWIN     512
#define NTOK     256
#define HD       24
#define NHEADS   4
#define HIDDEN_DIM 384

typedef unsigned long long ull;

// Scratch (device globals)
__device__ float g_qkv [(size_t)3 * TOKENS * CDIM];
__device__ float g_attn[(size_t)TOKENS * CDIM];
__device__ float g_x2  [(size_t)TOKENS * CDIM];
__device__ float g_h   [(size_t)TOKENS * HIDDEN_DIM];

__device__ __forceinline__ int nat_index(int t) {
    int r = t & 255, w = t >> 8;
    int b = w >> 8, wi = w & 255;
    int d  = ((((wi >> 6) & 3) << 2) | ((r >> 6) & 3));
    int hh = ((((wi >> 4) & 3) << 2) | ((r >> 4) & 3));
    int ww = ((((wi >> 2) & 3) << 2) | ((r >> 2) & 3));
    int tt = (((wi & 3) << 2) | (r & 3));
    d = (d + 2) & 15; hh = (hh + 2) & 15; ww = (ww + 2) & 15; tt = (tt + 2) & 15;
    return (((b * 16 + d) * 16 + hh) * 16 + ww) * 16 + tt;
}

__device__ __forceinline__ int group_of(int wi, int r) {
    int g = 0;
#pragma unroll
    for (int a = 3; a >= 0; --a) {
        int c = ((((wi >> (2 * a)) & 3) << 2) | ((r >> (2 * a)) & 3));
        int s = (c < 12) ? 0 : ((c < 14) ? 1 : 2);
        g = g * 3 + s;
    }
    return g;
}

__device__ __forceinline__ void mma_tf32(float4& d, const uint32_t a[4], const uint32_t b[2]) {
    asm("mma.sync.aligned.m16n8k8.row.col.f32.tf32.tf32.f32 "
        "{%0,%1,%2,%3},{%4,%5,%6,%7},{%8,%9},{%0,%1,%2,%3};"
        : "+f"(d.x), "+f"(d.y), "+f"(d.z), "+f"(d.w)
        : "r"(a[0]), "r"(a[1]), "r"(a[2]), "r"(a[3]), "r"(b[0]), "r"(b[1]));
}

// cp.async helpers
__device__ __forceinline__ void cp16(uint32_t dst, const void* src) {
    asm volatile("cp.async.cg.shared.global [%0],[%1],16;" :: "r"(dst), "l"(src));
}
__device__ __forceinline__ void cp_commit() { asm volatile("cp.async.commit_group;"); }
template <int N>
__device__ __forceinline__ void cp_wait() { asm volatile("cp.async.wait_group %0;" :: "n"(N)); }

enum { EPI_QKV = 0, EPI_PROJ = 1, EPI_FC1 = 2, EPI_FC2 = 3 };

// ---------------------------------------------------------------------------
// A-resident tf32 GEMM (unchanged from R8).
// ---------------------------------------------------------------------------
#define ASTR2 100

template <int E, bool LNF, bool GATHER, int NB>
__global__ void __launch_bounds__(256, 2) gemm_fz(const float* __restrict__ A,
                                                  const float* __restrict__ W,
                                                  const float* __restrict__ bias,
                                                  const float* __restrict__ res,
                                                  const float* __restrict__ gamma,
                                                  const float* __restrict__ beta,
                                                  float* __restrict__ out) {
    extern __shared__ float smem[];
    float* As   = smem;
    float* ring = smem + 128 * ASTR2;
    constexpr int WCH = 96 * 32;
    constexpr int NC  = NB * 3;

    const int tid  = threadIdx.x;
    const int warp = tid >> 5, lane = tid & 31;
    const int gid  = lane >> 2, tig = lane & 3;
    const int wm   = (warp >> 1) * 32;
    const int wb   = warp & 1;
    const int wn   = wb * 48;
    const int m0   = blockIdx.x * 128;

    uint32_t as_u   = (uint32_t)__cvta_generic_to_shared(As);
    uint32_t ring_u = (uint32_t)__cvta_generic_to_shared(ring);

#pragma unroll
    for (int it = 0; it < 12; ++it) {
        int idx = tid + it * 256;
        int row = idx / 24, c4 = (idx % 24) << 2;
        int m = m0 + row;
        const float* src = A + (size_t)(GATHER ? nat_index(m) : m) * CDIM + c4;
        cp16(as_u + (row * ASTR2 + c4) * 4, src);
    }
    cp_commit();

    const int wrow = tid >> 3, wj = tid & 7;
    auto issueW = [&](int c) {
        uint32_t wbuf = ring_u + ((c & 1) * WCH) * 4;
        int n0 = (c / 3) * 96, kc = (c % 3) * 32;
#pragma unroll
        for (int it = 0; it < 3; ++it) {
            int r = wrow + it * 32;
            uint32_t dst = wbuf + (r * 32 + (((wj + r) & 7) << 2)) * 4;
            cp16(dst, W + (size_t)(n0 + r) * CDIM + kc + (wj << 2));
        }
    };
    issueW(0); cp_commit();

    if (LNF) {
        cp_wait<1>();
        __syncthreads();
        int row = tid >> 1, half = tid & 1;
        float s = 0.f, sq = 0.f;
#pragma unroll
        for (int i = 0; i < 48; ++i) {
            float v = As[row * ASTR2 + half * 48 + i];
            s += v; sq += v * v;
        }
        s  += __shfl_xor_sync(0xffffffffu, s, 1);
        sq += __shfl_xor_sync(0xffffffffu, sq, 1);
        float mean = s * (1.f / 96.f);
        float var  = sq * (1.f / 96.f) - mean * mean;
        float rstd = rsqrtf(var + 1e-5f);
#pragma unroll
        for (int i = 0; i < 48; ++i) {
            int col = half * 48 + i;
            As[row * ASTR2 + col] = (As[row * ASTR2 + col] - mean) * rstd * __ldg(gamma + col) + __ldg(beta + col);
        }
        __syncthreads();
    }

    const uint32_t* Asu = (const uint32_t*)As;

    float4 acc[2][6];
#pragma unroll
    for (int i = 0; i < 2; ++i)
#pragma unroll
        for (int j = 0; j < 6; ++j) acc[i][j] = make_float4(0.f, 0.f, 0.f, 0.f);

    for (int c = 0; c < NC; ++c) {
        if (c + 1 < NC) issueW(c + 1);
        cp_commit();
        cp_wait<1>();
        __syncthreads();

        const uint32_t* Ws = (const uint32_t*)(ring + (c & 1) * WCH);

#pragma unroll
        for (int ks4 = 0; ks4 < 4; ++ks4) {
            const int kg = (c % 3) * 32 + ks4 * 8;
            uint32_t a[2][4];
#pragma unroll
            for (int mi = 0; mi < 2; ++mi) {
                int r = wm + mi * 16 + gid;
                a[mi][0] = Asu[r * ASTR2 + kg + tig];
                a[mi][1] = Asu[(r + 8) * ASTR2 + kg + tig];
                a[mi][2] = Asu[r * ASTR2 + kg + tig + 4];
                a[mi][3] = Asu[(r + 8) * ASTR2 + kg + tig + 4];
            }
            uint32_t b[6][2];
#pragma unroll
            for (int ni = 0; ni < 6; ++ni) {
                int n = wn + ni * 8 + gid;
                int ch0 = (2 * ks4 + gid) & 7;
                int ch1 = (2 * ks4 + 1 + gid) & 7;
                b[ni][0] = Ws[n * 32 + (ch0 << 2) + tig];
                b[ni][1] = Ws[n * 32 + (ch1 << 2) + tig];
            }
#pragma unroll
            for (int mi = 0; mi < 2; ++mi)
#pragma unroll
                for (int ni = 0; ni < 6; ++ni) mma_tf32(acc[mi][ni], a[mi], b[ni]);
        }

        if ((c % 3) == 2) {
            const int nb = c / 3, n0 = nb * 96;
#pragma unroll
            for (int mi = 0; mi < 2; ++mi) {
                int r0 = m0 + wm + mi * 16 + gid;
#pragma unroll
                for (int half = 0; half < 2; ++half) {
                    int m = r0 + half * 8;
                    size_t proj_dst = 0;
                    if (E == EPI_PROJ) proj_dst = (size_t)nat_index(m) * CDIM;
                    int w = m >> 8, rr = m & 255;
#pragma unroll
                    for (int ni = 0; ni < 6; ++ni) {
                        float v0 = half ? acc[mi][ni].z : acc[mi][ni].x;
                        float v1 = half ? acc[mi][ni].w : acc[mi][ni].y;
#pragma unroll
                        for (int e = 0; e < 2; ++e) {
                            int nl = wn + ni * 8 + tig * 2 + e;
                            float v = (e ? v1 : v0) + bias[n0 + nl];
                            if (E == EPI_QKV) {
                                const float scale = (nb == 0) ? 0.20412414523193154f : 1.0f;
                                int h = nl / 24, dd = nl % 24;
                                out[(((size_t)nb * NWIN + w) * NHEADS + h) * (NTOK * HD) + rr * HD + dd] = v * scale;
                            } else if (E == EPI_PROJ) {
                                out[proj_dst + nl] = res[proj_dst + nl] + v;
                            } else if (E == EPI_FC1) {
                                float gel = 0.5f * v * (1.f + erff(v * 0.70710678118654752f));
                                out[(size_t)m * HIDDEN_DIM + n0 + nl] = gel;
                            } else {
                                out[(size_t)m * CDIM + nl] = res[(size_t)m * CDIM + nl] + v;
                            }
                        }
                    }
                }
            }
            if (c + 1 < NC) {
#pragma unroll
                for (int i = 0; i < 2; ++i)
#pragma unroll
                    for (int j = 0; j < 6; ++j) acc[i][j] = make_float4(0.f, 0.f, 0.f, 0.f);
            }
        }
        __syncthreads();
    }
}

// ---------------------------------------------------------------------------
// Streaming tf32 GEMM for fc2 (unchanged from R8).
// ---------------------------------------------------------------------------
#define ASTR 36

__global__ void __launch_bounds__(256, 2) gemm_fc2(const float* __restrict__ A,
                                                   const float* __restrict__ W,
                                                   const float* __restrict__ bias,
                                                   const float* __restrict__ res,
                                                   float* __restrict__ out) {
    extern __shared__ float smem[];
    constexpr int ACH = 128 * ASTR, WCH = 96 * 32, STG = ACH + WCH;
    constexpr int KD = HIDDEN_DIM, NC = KD / 32, NSTG = 3, PF = 2;

    const int tid  = threadIdx.x;
    const int warp = tid >> 5, lane = tid & 31;
    const int gid  = lane >> 2, tig = lane & 3;
    const int wm   = (warp >> 1) * 32;
    const int wb   = warp & 1;
    const int wn   = wb * 48;
    const int m0   = blockIdx.x * 128;

    uint32_t smem_u = (uint32_t)__cvta_generic_to_shared(smem);
    const int crow = tid >> 3, cj = tid & 7, cc4 = cj << 2;

    auto issue = [&](int c) {
        int s = c % NSTG, kc = c * 32;
        uint32_t abuf = smem_u + (s * STG) * 4;
#pragma unroll
        for (int it = 0; it < 4; ++it) {
            int row = crow + it * 32;
            cp16(abuf + (row * ASTR + cc4) * 4, A + (size_t)(m0 + row) * KD + kc + cc4);
        }
        uint32_t wbuf = abuf + ACH * 4;
#pragma unroll
        for (int it = 0; it < 3; ++it) {
            int r = crow + it * 32;
            cp16(wbuf + (r * 32 + (((cj + r) & 7) << 2)) * 4,
                 W + (size_t)r * KD + kc + cc4);
        }
    };

    issue(0); cp_commit();
    issue(1); cp_commit();

    float4 acc[2][6];
#pragma unroll
    for (int i = 0; i < 2; ++i)
#pragma unroll
        for (int j = 0; j < 6; ++j) acc[i][j] = make_float4(0.f, 0.f, 0.f, 0.f);

    for (int c = 0; c < NC; ++c) {
        if (c + PF < NC) issue(c + PF);
        cp_commit();
        cp_wait<PF>();
        __syncthreads();

        const uint32_t* As = (const uint32_t*)(smem + (c % NSTG) * STG);
        const uint32_t* Ws = (const uint32_t*)(smem + (c % NSTG) * STG + ACH);

#pragma unroll
        for (int ks4 = 0; ks4 < 4; ++ks4) {
            const int k = ks4 * 8;
            uint32_t a[2][4];
#pragma unroll
            for (int mi = 0; mi < 2; ++mi) {
                int r = wm + mi * 16 + gid;
                a[mi][0] = As[r * ASTR + k + tig];
                a[mi][1] = As[(r + 8) * ASTR + k + tig];
                a[mi][2] = As[r * ASTR + k + tig + 4];
                a[mi][3] = As[(r + 8) * ASTR + k + tig + 4];
            }
            uint32_t b[6][2];
#pragma unroll
            for (int ni = 0; ni < 6; ++ni) {
                int n = wn + ni * 8 + gid;
                int ch0 = (2 * ks4 + gid) & 7;
                int ch1 = (2 * ks4 + 1 + gid) & 7;
                b[ni][0] = Ws[n * 32 + (ch0 << 2) + tig];
                b[ni][1] = Ws[n * 32 + (ch1 << 2) + tig];
            }
#pragma unroll
            for (int mi = 0; mi < 2; ++mi)
#pragma unroll
                for (int ni = 0; ni < 6; ++ni) mma_tf32(acc[mi][ni], a[mi], b[ni]);
        }
        __syncthreads();
    }

#pragma unroll
    for (int mi = 0; mi < 2; ++mi) {
        int r0 = m0 + wm + mi * 16 + gid;
#pragma unroll
        for (int half = 0; half < 2; ++half) {
            int m = r0 + half * 8;
#pragma unroll
            for (int ni = 0; ni < 6; ++ni) {
                float v0 = half ? acc[mi][ni].z : acc[mi][ni].x;
                float v1 = half ? acc[mi][ni].w : acc[mi][ni].y;
#pragma unroll
                for (int e = 0; e < 2; ++e) {
                    int nl = wn + ni * 8 + tig * 2 + e;
                    float v = (e ? v1 : v0) + bias[nl];
                    out[(size_t)m * CDIM + nl] = res[(size_t)m * CDIM + nl] + v;
                }
            }
        }
    }
}

// ---------------------------------------------------------------------------
// Tensor-core attention. CTA = (window, head), 8 warps.
// S = Q·K^T via tf32 mma (warp tile 64x32 over key blocks of 64); exp+mask in
// regs; P round-trips smem WITHIN each warp (syncwarp only); PV via tf32 mma,
// k-split across the two n-half warps; combine + softmax-normalize at end.
// ---------------------------------------------------------------------------
#define QSTR 28
#define PSTR 68

__global__ void __launch_bounds__(256) attn_mma(const float* __restrict__ qkv,
                                                float* __restrict__ attnout) {
    extern __shared__ float sm[];
    float* Qs = sm;                        // [256][28]
    float* Ks = Qs + 256 * QSTR;           // [256][28]
    float* Vs = Ks + 256 * QSTR;           // [256][24]
    float* Ps = Vs + 256 * 24;             // [256][68]
    float* Ls = Ps + 256 * PSTR;           // [2][256]
    unsigned char* grp = (unsigned char*)(Ls + 512);  // 256

    const int w = blockIdx.x, h = blockIdx.y;
    const int tid = threadIdx.x, warp = tid >> 5, lane = tid & 31;
    const int gid = lane >> 2, tig = lane & 3;
    const int wm = (warp >> 1) * 64;       // 4 warps over M (queries)
    const int wb = warp & 1;               // n-half / k-half
    const size_t hs = (size_t)NTOK * HD;
    const float* qb = qkv + (((size_t)0 * NWIN + w) * NHEADS + h) * hs;
    const float* kg = qkv + (((size_t)1 * NWIN + w) * NHEADS + h) * hs;
    const float* vg = qkv + (((size_t)2 * NWIN + w) * NHEADS + h) * hs;

#pragma unroll
    for (int it = 0; it < 6; ++it) {
        int idx = tid + it * 256;
        int row = idx / 6, c4 = (idx % 6) * 4;
        float4 q4 = *(const float4*)(qb + row * 24 + c4);
        float4 k4 = *(const float4*)(kg + row * 24 + c4);
        float4 v4 = *(const float4*)(vg + row * 24 + c4);
        Qs[row*QSTR+c4+0]=q4.x; Qs[row*QSTR+c4+1]=q4.y; Qs[row*QSTR+c4+2]=q4.z; Qs[row*QSTR+c4+3]=q4.w;
        Ks[row*QSTR+c4+0]=k4.x; Ks[row*QSTR+c4+1]=k4.y; Ks[row*QSTR+c4+2]=k4.z; Ks[row*QSTR+c4+3]=k4.w;
        *(float4*)(Vs + row * 24 + c4) = v4;
    }
    grp[tid] = (unsigned char)group_of(w & 255, tid);
    __syncthreads();

    const uint32_t* Qu = (const uint32_t*)Qs;
    const uint32_t* Ku = (const uint32_t*)Ks;
    const uint32_t* Vu = (const uint32_t*)Vs;
    const uint32_t* Pu = (const uint32_t*)Ps;

    float4 oacc[4][3];
#pragma unroll
    for (int i = 0; i < 4; ++i)
#pragma unroll
        for (int j = 0; j < 3; ++j) oacc[i][j] = make_float4(0.f, 0.f, 0.f, 0.f);
    float rs[4][2];
#pragma unroll
    for (int i = 0; i < 4; ++i) { rs[i][0] = 0.f; rs[i][1] = 0.f; }

    for (int kb = 0; kb < 4; ++kb) {
        float4 sacc[4][4];
#pragma unroll
        for (int i = 0; i < 4; ++i)
#pragma unroll
            for (int j = 0; j < 4; ++j) sacc[i][j] = make_float4(0.f, 0.f, 0.f, 0.f);

        // ---- S = Q K^T (this warp: rows wm..wm+63, keys kb*64+wb*32..+31) ----
#pragma unroll
        for (int kk = 0; kk < 3; ++kk) {
            const int k8 = kk * 8;
            uint32_t a[4][4], b[4][2];
#pragma unroll
            for (int mi = 0; mi < 4; ++mi) {
                int r = wm + mi * 16 + gid;
                a[mi][0] = Qu[r * QSTR + k8 + tig];
                a[mi][1] = Qu[(r + 8) * QSTR + k8 + tig];
                a[mi][2] = Qu[r * QSTR + k8 + tig + 4];
                a[mi][3] = Qu[(r + 8) * QSTR + k8 + tig + 4];
            }
#pragma unroll
            for (int ni = 0; ni < 4; ++ni) {
                int n = kb * 64 + wb * 32 + ni * 8 + gid;
                b[ni][0] = Ku[n * QSTR + k8 + tig];
                b[ni][1] = Ku[n * QSTR + k8 + tig + 4];
            }
#pragma unroll
            for (int mi = 0; mi < 4; ++mi)
#pragma unroll
                for (int ni = 0; ni < 4; ++ni) mma_tf32(sacc[mi][ni], a[mi], b[ni]);
        }

        // ---- mask + exp + row-sum partials + store P (own warp's slice) ----
#pragma unroll
        for (int mi = 0; mi < 4; ++mi) {
            int r0 = wm + mi * 16 + gid;
            int rg0 = grp[r0], rg1 = grp[r0 + 8];
#pragma unroll
            for (int ni = 0; ni < 4; ++ni) {
                int cc = kb * 64 + wb * 32 + ni * 8 + 2 * tig;
                int cg0 = grp[cc], cg1 = grp[cc + 1];
                float4 s = sacc[mi][ni];
                float p00 = __expf(s.x + (cg0 == rg0 ? 0.f : -100.f));
                float p01 = __expf(s.y + (cg1 == rg0 ? 0.f : -100.f));
                float p10 = __expf(s.z + (cg0 == rg1 ? 0.f : -100.f));
                float p11 = __expf(s.w + (cg1 == rg1 ? 0.f : -100.f));
                rs[mi][0] += p00 + p01;
                rs[mi][1] += p10 + p11;
                int pc = wb * 32 + ni * 8 + 2 * tig;
                *(float2*)(Ps + r0 * PSTR + pc)       = make_float2(p00, p01);
                *(float2*)(Ps + (r0 + 8) * PSTR + pc) = make_float2(p10, p11);
            }
        }
        __syncwarp();

        // ---- PV: this warp consumes exactly its own P slice ----
#pragma unroll
        for (int kk = 0; kk < 4; ++kk) {
            const int kp = wb * 32 + kk * 8;
            const int kv = kb * 64 + kp;
            uint32_t a[4][4], b[3][2];
#pragma unroll
            for (int mi = 0; mi < 4; ++mi) {
                int r = wm + mi * 16 + gid;
                a[mi][0] = Pu[r * PSTR + kp + tig];
                a[mi][1] = Pu[(r + 8) * PSTR + kp + tig];
                a[mi][2] = Pu[r * PSTR + kp + tig + 4];
                a[mi][3] = Pu[(r + 8) * PSTR + kp + tig + 4];
            }
#pragma unroll
            for (int nd = 0; nd < 3; ++nd) {
                int n = nd * 8 + gid;
                b[nd][0] = Vu[(kv + tig) * 24 + n];
                b[nd][1] = Vu[(kv + tig + 4) * 24 + n];
            }
#pragma unroll
            for (int mi = 0; mi < 4; ++mi)
#pragma unroll
                for (int nd = 0; nd < 3; ++nd) mma_tf32(oacc[mi][nd], a[mi], b[nd]);
        }
        __syncwarp();
    }

    // ---- row-sum reduce across tig lanes, publish per-warp-half sums ----
#pragma unroll
    for (int mi = 0; mi < 4; ++mi)
#pragma unroll
        for (int hf = 0; hf < 2; ++hf) {
            float v = rs[mi][hf];
            v += __shfl_xor_sync(0xffffffffu, v, 1);
            v += __shfl_xor_sync(0xffffffffu, v, 2);
            rs[mi][hf] = v;
        }
    if (tig == 0) {
#pragma unroll
        for (int mi = 0; mi < 4; ++mi) {
            Ls[wb * 256 + wm + mi * 16 + gid]     = rs[mi][0];
            Ls[wb * 256 + wm + mi * 16 + gid + 8] = rs[mi][1];
        }
    }
    __syncthreads();

    // ---- combine the two k-half partial PV results, normalize, write ----
    float* OS = Qs;                        // reuse Q staging area
    const int OSTR = 26;
    if (wb == 1) {
#pragma unroll
        for (int mi = 0; mi < 4; ++mi) {
            int r0 = wm + mi * 16 + gid;
#pragma unroll
            for (int nd = 0; nd < 3; ++nd) {
                int c = nd * 8 + 2 * tig;
                *(float2*)(OS + r0 * OSTR + c)       = make_float2(oacc[mi][nd].x, oacc[mi][nd].y);
                *(float2*)(OS + (r0 + 8) * OSTR + c) = make_float2(oacc[mi][nd].z, oacc[mi][nd].w);
            }
        }
    }
    __syncthreads();
    if (wb == 0) {
#pragma unroll
        for (int mi = 0; mi < 4; ++mi) {
            int r0 = wm + mi * 16 + gid, r1 = r0 + 8;
            float inv0 = 1.f / (Ls[r0] + Ls[256 + r0]);
            float inv1 = 1.f / (Ls[r1] + Ls[256 + r1]);
#pragma unroll
            for (int nd = 0; nd < 3; ++nd) {
                int c = nd * 8 + 2 * tig;
                float2 t0 = *(float2*)(OS + r0 * OSTR + c);
                float2 t1 = *(float2*)(OS + r1 * OSTR + c);
                float* o0 = attnout + ((size_t)w * NTOK + r0) * CDIM + h * HD + c;
                float* o1 = attnout + ((size_t)w * NTOK + r1) * CDIM + h * HD + c;
                o0[0] = (oacc[mi][nd].x + t0.x) * inv0;
                o0[1] = (oacc[mi][nd].y + t0.y) * inv0;
                o1[0] = (oacc[mi][nd].z + t1.x) * inv1;
                o1[1] = (oacc[mi][nd].w + t1.y) * inv1;
            }
        }
    }
}

// ---------------------------------------------------------------------------
extern "C" void kernel_launch(void* const* d_in, const int* in_sizes, int n_in,
                              void* d_out, int out_size) {
    (void)in_sizes; (void)n_in; (void)out_size;
    const float* x       = (const float*)d_in[0];
    const float* norm1_g = (const float*)d_in[2];
    const float* norm1_b = (const float*)d_in[3];
    const float* qkv_w   = (const float*)d_in[4];
    const float* qkv_b   = (const float*)d_in[5];
    const float* proj_w  = (const float*)d_in[6];
    const float* proj_b  = (const float*)d_in[7];
    const float* norm2_g = (const float*)d_in[8];
    const float* norm2_b = (const float*)d_in[9];
    const float* fc1_w   = (const float*)d_in[10];
    const float* fc1_b   = (const float*)d_in[11];
    const float* fc2_w   = (const float*)d_in[12];
    const float* fc2_b   = (const float*)d_in[13];
    float* out = (float*)d_out;

    float *qkv, *attn, *x2, *hbuf;
    cudaGetSymbolAddress((void**)&qkv,  g_qkv);
    cudaGetSymbolAddress((void**)&attn, g_attn);
    cudaGetSymbolAddress((void**)&x2,   g_x2);
    cudaGetSymbolAddress((void**)&hbuf, g_h);

    const int fz_smem  = (128 * ASTR2 + 2 * 96 * 32) * 4;            // 75776 B
    const int fc2_smem = 3 * (128 * ASTR + 96 * 32) * 4;             // 92160 B
    cudaFuncSetAttribute(gemm_fz<EPI_QKV,  true,  true,  3>, cudaFuncAttributeMaxDynamicSharedMemorySize, fz_smem);
    cudaFuncSetAttribute(gemm_fz<EPI_PROJ, false, false, 1>, cudaFuncAttributeMaxDynamicSharedMemorySize, fz_smem);
    cudaFuncSetAttribute(gemm_fz<EPI_FC1,  true,  false, 4>, cudaFuncAttributeMaxDynamicSharedMemorySize, fz_smem);
    cudaFuncSetAttribute(gemm_fc2, cudaFuncAttributeMaxDynamicSharedMemorySize, fc2_smem);

    // attn smem: Q 7168 + K 7168 + V 6144 + P 17408 + L 512 + grp 64 floats
    const int attn_smem = (256 * QSTR * 2 + 256 * 24 + 256 * PSTR + 512 + 64) * 4;  // 153856 B
    cudaFuncSetAttribute(attn_mma, cudaFuncAttributeMaxDynamicSharedMemorySize, attn_smem);

    // 1) QKV: fused LN1 + shift + partition (gather), all 3 N-blocks per CTA
    gemm_fz<EPI_QKV, true, true, 3><<<1024, 256, fz_smem>>>(
        x, qkv_w, qkv_b, nullptr, norm1_g, norm1_b, qkv);
    // 2) windowed attention on tensor cores, analytic shift mask
    attn_mma<<<dim3(NWIN, NHEADS), 256, attn_smem>>>(qkv, attn);
    // 3) proj + reverse partition/shift + residual
    gemm_fz<EPI_PROJ, false, false, 1><<<1024, 256, fz_smem>>>(
        attn, proj_w, proj_b, x, nullptr, nullptr, x2);
    // 4) fc1: fused LN2 + exact GELU, all 4 N-blocks per CTA
    gemm_fz<EPI_FC1, true, false, 4><<<1024, 256, fz_smem>>>(
        x2, fc1_w, fc1_b, nullptr, norm2_g, norm2_b, hbuf);
    // 5) fc2 + residual -> output
    gemm_fc2<<<1024, 256, fc2_smem>>>(hbuf, fc2_w, fc2_b, x2, out);
}